// round 16
// baseline (speedup 1.0000x reference)
#include <cuda_runtime.h>
#include <cuda_fp16.h>
#include <cstdint>

#define DINLINE __device__ __forceinline__

// ---------------- problem constants ----------------
constexpr int BQ  = 8192;   // batch rows
constexpr int HID = 1024;   // hidden
constexpr int N9  = 9216;   // packed N: 7 sum gates + x3 + m3
constexpr int KC  = 4096;   // correction K (fp16-acc phase): [xl | xh | ml | mh]
constexpr int KM  = 2048;   // main K (f32-acc phase): [xh | mh]

// GEMM tiling: 128x128 CTA tile, 4 warps, 3 stages, 2 CTA/SM, persistent
constexpr int BM = 128, BN = 128, NSTAGE = 3;
constexpr int A_STAGE_BYTES = BM * 128;                      // 16384 (128B/row)
constexpr int STAGE_BYTES   = 2 * A_STAGE_BYTES;             // 32768
constexpr int SMEM_DYN      = NSTAGE * STAGE_BYTES + 1024;

constexpr int MT = BQ / BM;   // 64
constexpr int NT = N9 / BN;   // 72
constexpr int GM = 8;         // m-supertile height
constexpr int NTILES = MT * NT;          // 4608
constexpr int GRID_P = 296;              // 148 SMs x 2 CTAs (all resident)

// merged pack grid split
constexpr int PACKA_BLOCKS = 8192;               // 8192*256 threads = BQ*256
constexpr int PACKB_BLOCKS = 256 * 32 * 2;       // 16384
constexpr int PACK_BLOCKS  = PACKA_BLOCKS + PACKB_BLOCKS;

// ---------------- device scratch (static globals: allowed) ----------------
__device__ __half g_Ac[(size_t)BQ * KC];   // 64 MB  corrections
__device__ __half g_Am[(size_t)BQ * KM];   // 32 MB  main
__device__ __half g_Bc[(size_t)N9 * KC];   // 72 MB
__device__ __half g_Bm[(size_t)N9 * KM];   // 36 MB
__device__ float  g_C [(size_t)BQ * N9];   // 288 MB
__device__ unsigned int g_tile_ctr;        // work-stealing cursor

// ---------------- PTX helpers (sm_80-class only) ----------------
DINLINE uint32_t smem_u32(const void* p) {
    uint32_t a;
    asm("{ .reg .u64 t; cvta.to.shared.u64 t, %1; cvt.u32.u64 %0, t; }"
        : "=r"(a) : "l"(p));
    return a;
}

DINLINE void cp16(uint32_t dst, const void* src) {
    asm volatile("cp.async.cg.shared.global [%0], [%1], 16;" :: "r"(dst), "l"(src));
}
DINLINE void cp_commit() { asm volatile("cp.async.commit_group;" ::: "memory"); }
DINLINE void cp_wait1()  { asm volatile("cp.async.wait_group 1;" ::: "memory"); }

DINLINE void ldsm4(uint32_t& r0, uint32_t& r1, uint32_t& r2, uint32_t& r3,
                   uint32_t addr) {
    asm volatile("ldmatrix.sync.aligned.m8n8.x4.shared.b16 {%0,%1,%2,%3}, [%4];"
                 : "=r"(r0), "=r"(r1), "=r"(r2), "=r"(r3) : "r"(addr));
}

// fp16 x fp16 -> f32 accumulate, acc stored as uint32 bits
DINLINE void mma_f32(uint32_t* c, const uint32_t* a, const uint32_t* b) {
    asm volatile(
        "{\n\t.reg .f32 p0,p1,p2,p3;\n\t"
        "mov.b32 p0,%0; mov.b32 p1,%1; mov.b32 p2,%2; mov.b32 p3,%3;\n\t"
        "mma.sync.aligned.m16n8k16.row.col.f32.f16.f16.f32 "
        "{p0,p1,p2,p3}, {%4,%5,%6,%7}, {%8,%9}, {p0,p1,p2,p3};\n\t"
        "mov.b32 %0,p0; mov.b32 %1,p1; mov.b32 %2,p2; mov.b32 %3,p3;\n\t}"
        : "+r"(c[0]), "+r"(c[1]), "+r"(c[2]), "+r"(c[3])
        : "r"(a[0]), "r"(a[1]), "r"(a[2]), "r"(a[3]), "r"(b[0]), "r"(b[1]));
}

// fp16 x fp16 -> f16 accumulate (2 packed regs)
DINLINE void mma_f16(uint32_t* c, const uint32_t* a, const uint32_t* b) {
    asm volatile(
        "mma.sync.aligned.m16n8k16.row.col.f16.f16.f16.f16 "
        "{%0,%1}, {%2,%3,%4,%5}, {%6,%7}, {%0,%1};"
        : "+r"(c[0]), "+r"(c[1])
        : "r"(a[0]), "r"(a[1]), "r"(a[2]), "r"(a[3]), "r"(b[0]), "r"(b[1]));
}

DINLINE __half2 u32_as_half2(uint32_t u) {
    __half2 h;
    *(uint32_t*)&h = u;
    return h;
}

// fast transcendentals: MUFU ex2 + MUFU rcp (__fdividef), saturate at +-inf
DINLINE float fsig(float v)  { return __fdividef(1.0f, 1.0f + __expf(-v)); }
DINLINE float ftanh(float v) { return 1.0f - __fdividef(2.0f, __expf(2.0f * v) + 1.0f); }

// tile descriptor for cross-tile pipelining
struct TileInfo {
    int m0, n0, nc, NS;
    const char *pAc, *pAm, *pBc, *pBm;
};

DINLINE void make_tile(unsigned int tile, TileInfo& ti) {
    int mt = (tile / (GM * NT)) * GM + (tile % GM);
    int nt = (tile / GM) % NT;
    ti.m0 = mt * BM;
    ti.n0 = nt * BN;
    int cbeg, mbeg, nm;
    if (ti.n0 >= 8192)      { cbeg = 4096; ti.nc = 32; mbeg = 2048; nm = 16; } // m3
    else if (ti.n0 >= 7168) { cbeg = 0;    ti.nc = 32; mbeg = 0;    nm = 16; } // x3
    else                    { cbeg = 0;    ti.nc = 64; mbeg = 0;    nm = 32; } // sums
    ti.NS = ti.nc + nm;   // 96 or 48 — both divisible by NSTAGE=3
    ti.pAc = (const char*)g_Ac + (size_t)ti.m0 * (KC * 2) + cbeg;
    ti.pAm = (const char*)g_Am + (size_t)ti.m0 * (KM * 2) + mbeg;
    ti.pBc = (const char*)g_Bc + (size_t)ti.n0 * (KC * 2) + cbeg;
    ti.pBm = (const char*)g_Bm + (size_t)ti.n0 * (KM * 2) + mbeg;
}

// ---------------- merged pack kernel ----------------
// blocks [0, PACKA_BLOCKS):           A-packing
// blocks [PACKA_BLOCKS, PACK_BLOCKS): B-packing (transpose tiles)
// Am row b: [xh | mh]. Ac row b: [xl | xh | ml | mh].
// Bm row n: [wih | wmh]. Bc row n: [wih | wil | wmh | wml]
// (corr pairing: xl*wih + xh*wil + ml*wmh + mh*wml)
__global__ void pack_AB(const float* __restrict__ x, const float* __restrict__ m,
                        const float* __restrict__ wi, const float* __restrict__ wm) {
    __shared__ float t[32][33];
    int blk = blockIdx.x;
    int tid = threadIdx.x;

    if (blk < PACKA_BLOCKS) {
        // ---- A path ----
        size_t idx = (size_t)blk * 256 + tid;
        if (idx == 0) g_tile_ctr = GRID_P;      // reset work-stealing cursor
        size_t b = idx >> 8;
        int k4 = (int)(idx & 255) * 4;

        float xs[4], ms[4];
        *(float4*)xs = *(const float4*)(x + b * 1024 + k4);
        *(float4*)ms = *(const float4*)(m + b * 1024 + k4);

        unsigned short xh[4], xl[4], mh[4], ml[4];
#pragma unroll
        for (int c = 0; c < 4; c++) {
            __half h = __float2half_rn(xs[c]);
            xh[c] = __half_as_ushort(h);
            xl[c] = __half_as_ushort(__float2half_rn(xs[c] - __half2float(h)));
            h = __float2half_rn(ms[c]);
            mh[c] = __half_as_ushort(h);
            ml[c] = __half_as_ushort(__float2half_rn(ms[c] - __half2float(h)));
        }
        *(uint2*)&g_Am[b * KM + k4]        = *(uint2*)xh;
        *(uint2*)&g_Am[b * KM + 1024 + k4] = *(uint2*)mh;
        *(uint2*)&g_Ac[b * KC + k4]        = *(uint2*)xl;
        *(uint2*)&g_Ac[b * KC + 1024 + k4] = *(uint2*)xh;
        *(uint2*)&g_Ac[b * KC + 2048 + k4] = *(uint2*)ml;
        *(uint2*)&g_Ac[b * KC + 3072 + k4] = *(uint2*)mh;
    } else {
        // ---- B path ----
        int b2 = blk - PACKA_BLOCKS;
        int ct = b2 & 255;              // col tile over 8192
        int kt = (b2 >> 8) & 31;        // k tile over 1024
        int z  = b2 >> 13;              // 0 = w_inputs, 1 = w_m
        const float* w = z ? wm : wi;
        int col0 = ct * 32, k0 = kt * 32;
        int tx = tid & 15, ty = tid >> 4;      // 16 x 16
        for (int r = ty; r < 32; r += 16) {
            t[r][tx]      = w[(size_t)(k0 + r) * 8192 + col0 + tx];
            t[r][tx + 16] = w[(size_t)(k0 + r) * 8192 + col0 + tx + 16];
        }
        __syncthreads();
        for (int r = ty; r < 32; r += 16) {
            int col = col0 + r;
            float v0 = t[2 * tx][r];         // = w[k0+2tx][col]
            float v1 = t[2 * tx + 1][r];     // = w[k0+2tx+1][col]
            __half h0 = __float2half_rn(v0), h1 = __float2half_rn(v1);
            __half l0 = __float2half_rn(v0 - __half2float(h0));
            __half l1 = __float2half_rn(v1 - __half2float(h1));
            __half2 hi2 = __halves2half2(h0, h1);
            __half2 lo2 = __halves2half2(l0, l1);
            int g = col >> 10, h = col & 1023;
            size_t n;
            if (g == 3) n = z ? (size_t)(8192 + h) : (size_t)(7168 + h);
            else        n = (size_t)((g < 3 ? g : g - 1) * 1024 + h);
            int kk = k0 + 2 * tx;
            *(__half2*)&g_Bm[n * KM + z * 1024 + kk]        = hi2;
            *(__half2*)&g_Bc[n * KC + z * 2048 + kk]        = hi2;
            *(__half2*)&g_Bc[n * KC + z * 2048 + 1024 + kk] = lo2;
        }
    }
}

// ---------------- GEMM: persistent + cross-tile pipelined -----------------
__global__ __launch_bounds__(128, 2)
void gemm_kernel() {
    extern __shared__ char dsmem[];
    __shared__ unsigned int s_next;
    char* tilep = (char*)(((uintptr_t)dsmem + 1023) & ~(uintptr_t)1023);
    uint32_t tile_base = smem_u32(tilep);

    int tid = threadIdx.x;
    int wid = tid >> 5;
    int lid = tid & 31;
    int wmo = (wid & 1) * 64;    // warp m-offset (2 warps in m)
    int wno = (wid >> 1) * 64;   // warp n-offset (2 warps in n)

    int rowA = wmo + (lid & 15);                      // + mf*16
    int kAby = (lid >> 4) * 16;                       // + ks*32 bytes
    int rowB = wno + (lid & 7) + (lid >> 4) * 8;      // + nf2*16
    int kBby = ((lid >> 3) & 1) * 16;                 // + ks*32 bytes

    auto fill_chunk = [&](int s, const TileInfo& ti, int j) {
        bool corr = (j < ti.nc);
        const char* gA = corr ? ti.pAc + j * 128 : ti.pAm + (j - ti.nc) * 128;
        const char* gB = corr ? ti.pBc + j * 128 : ti.pBm + (j - ti.nc) * 128;
        size_t stride = corr ? (size_t)(KC * 2) : (size_t)(KM * 2);
        uint32_t baseA = tile_base + s * STAGE_BYTES;
        uint32_t baseB = baseA + A_STAGE_BYTES;
#pragma unroll
        for (int q = 0; q < 16; q++) {
            int ch = tid + (q << 7);           // 0..2047
            int rr = (ch >> 3) & 127;
            int cc = ch & 7;
            uint32_t off = (uint32_t)((rr << 7) + (cc << 4));
            uint32_t sw  = off ^ ((off >> 3) & 0x70);
            const char* src = ((ch < 1024) ? gA : gB) + (size_t)rr * stride + (cc << 4);
            cp16(((ch < 1024) ? baseA : baseB) + sw, src);
        }
    };

    uint32_t aF[2][4][4];
    uint32_t bF[2][8][2];

    auto load_frags = [&](int buf, uint32_t sA, uint32_t sB, int ks) {
#pragma unroll
        for (int mf = 0; mf < 4; mf++) {
            uint32_t off = (uint32_t)((rowA + mf * 16) << 7);
            uint32_t addr = sA + off + (((uint32_t)(kAby + ks * 32)) ^ ((off >> 3) & 0x70));
            ldsm4(aF[buf][mf][0], aF[buf][mf][1], aF[buf][mf][2], aF[buf][mf][3], addr);
        }
#pragma unroll
        for (int nf2 = 0; nf2 < 4; nf2++) {
            uint32_t off = (uint32_t)((rowB + nf2 * 16) << 7);
            uint32_t addr = sB + off + (((uint32_t)(kBby + ks * 32)) ^ ((off >> 3) & 0x70));
            uint32_t r0, r1, r2, r3;
            ldsm4(r0, r1, r2, r3, addr);
            bF[buf][nf2 * 2][0] = r0;      bF[buf][nf2 * 2][1] = r1;
            bF[buf][nf2 * 2 + 1][0] = r2;  bF[buf][nf2 * 2 + 1][1] = r3;
        }
    };

    unsigned int tile = blockIdx.x;
    TileInfo cur;
    make_tile(tile, cur);

    // steal the NEXT tile up-front (visible to all threads by the first
    // mainloop __syncthreads, read only at i = NS-2)
    if (tid == 0) s_next = atomicAdd(&g_tile_ctr, 1u);

    // initial prologue: chunks 0,1 of the first tile
    fill_chunk(0, cur, 0); cp_commit();
    fill_chunk(1, cur, 1); cp_commit();

    while (true) {
        // accumulator union: f16 pair in [0..1] during corr phase,
        // f32 bits in [0..3] after the in-place expansion
        uint32_t acc[4][8][4];
#pragma unroll
        for (int mf = 0; mf < 4; mf++)
#pragma unroll
            for (int nf = 0; nf < 8; nf++) {
                acc[mf][nf][0] = 0u; acc[mf][nf][1] = 0u;
                acc[mf][nf][2] = 0u; acc[mf][nf][3] = 0u;
            }

        unsigned int ntile = 0xFFFFFFFFu;   // sentinel: not yet read
        TileInfo nx;

        for (int i = 0; i < cur.NS; i++) {
            int s = i - (i / NSTAGE) * NSTAGE;        // i % 3 (NS % 3 == 0)
            // SAFE order: wait fill(i); barrier (readers of stage (i+2)%3
            // done); frag loads; only then refill that stage.
            cp_wait1();
            __syncthreads();

            if (i == cur.nc) {   // phase boundary: expand fp16 acc -> f32 bits
#pragma unroll
                for (int mf = 0; mf < 4; mf++)
#pragma unroll
                    for (int nf = 0; nf < 8; nf++) {
                        float2 lo = __half22float2(u32_as_half2(acc[mf][nf][0]));
                        float2 hi = __half22float2(u32_as_half2(acc[mf][nf][1]));
                        acc[mf][nf][0] = __float_as_uint(lo.x);
                        acc[mf][nf][1] = __float_as_uint(lo.y);
                        acc[mf][nf][2] = __float_as_uint(hi.x);
                        acc[mf][nf][3] = __float_as_uint(hi.y);
                    }
            }

            uint32_t sA = tile_base + s * STAGE_BYTES;
            uint32_t sB = sA + A_STAGE_BYTES;
            load_frags(0, sA, sB, 0);                 // start compute feed

            // cross-tile fill: tail iterations prefetch the NEXT tile
            int j = i + 2;
            int s2 = s + 2; if (s2 >= NSTAGE) s2 -= NSTAGE;
            if (j < cur.NS) {
                fill_chunk(s2, cur, j);
            } else {
                if (ntile == 0xFFFFFFFFu) {
                    ntile = s_next;                   // all threads read same value
                    if (ntile < NTILES) make_tile(ntile, nx);
                }
                if (ntile < NTILES) fill_chunk(s2, nx, j - cur.NS);
            }
            cp_commit();                              // exactly one group per iter

            if (i < cur.nc) {
#pragma unroll
                for (int ks = 0; ks < 4; ks++) {
                    int c2 = ks & 1;
                    if (ks < 3) load_frags(c2 ^ 1, sA, sB, ks + 1);
#pragma unroll
                    for (int mf = 0; mf < 4; mf++)
#pragma unroll
                        for (int nf = 0; nf < 8; nf++)
                            mma_f16(acc[mf][nf], aF[c2][mf], bF[c2][nf]);
                }
            } else {
#pragma unroll
                for (int ks = 0; ks < 4; ks++) {
                    int c2 = ks & 1;
                    if (ks < 3) load_frags(c2 ^ 1, sA, sB, ks + 1);
#pragma unroll
                    for (int mf = 0; mf < 4; mf++)
#pragma unroll
                        for (int nf = 0; nf < 8; nf++)
                            mma_f32(acc[mf][nf], aF[c2][mf], bF[c2][nf]);
                }
            }
        }

        // epilogue: float2 stores (overlapped with next tile's in-flight fills)
        int rr = lid >> 2;
        int cc2 = (lid & 3) * 2;
#pragma unroll
        for (int mf = 0; mf < 4; mf++) {
#pragma unroll
            for (int nf = 0; nf < 8; nf++) {
                int m = cur.m0 + wmo + mf * 16 + rr;
                int n = cur.n0 + wno + nf * 8 + cc2;
                float2 v0 = make_float2(__uint_as_float(acc[mf][nf][0]),
                                        __uint_as_float(acc[mf][nf][1]));
                float2 v1 = make_float2(__uint_as_float(acc[mf][nf][2]),
                                        __uint_as_float(acc[mf][nf][3]));
                *(float2*)&g_C[(size_t)m * N9 + n] = v0;
                *(float2*)&g_C[(size_t)(m + 8) * N9 + n] = v1;
            }
        }

        if (ntile >= NTILES) return;     // consistent across all threads

        tile = ntile;
        cur = nx;
        // steal the tile AFTER next; ordering vs reads is guaranteed by the
        // per-iteration barriers of the upcoming mainloop (write < bar(i=0)
        // < read at i = NS-2)
        if (tid == 0) s_next = atomicAdd(&g_tile_ctr, 1u);
    }
}

// ---------------- combine: gate network (float2, fast transcendentals) ----
DINLINE float gate_net(float s0, float s1, float s2, float s4, float s5,
                       float s6, float s7, float x3, float m3,
                       float cp, float& nc) {
    float l10 = fsig(s0);
    float l11 = fmaxf(s1, 0.0f);
    float l12 = fsig(s2);
    float l13 = fmaxf(x3 * m3, 0.0f);
    float l14 = ftanh(s4);
    float l15 = fsig(s5);
    float l16 = ftanh(s6);
    float l17 = fsig(s7);
    float l20 = ftanh(l10 * l11);
    float l21 = ftanh(l12 + l13);
    float l22 = ftanh(l14 * l15);
    float l23 = fsig(l16 + l17);
    l20 = ftanh(l20 + cp);
    nc = l20 * l21;
    float l31 = ftanh(l22 + l23);
    return ftanh(nc * l31);
}

__global__ void combine_kernel(const float* __restrict__ c_prev, float* __restrict__ out) {
    int idx = blockIdx.x * blockDim.x + threadIdx.x;      // < BQ*512
    if (idx >= BQ * 512) return;
    int b  = idx >> 9;
    int h2 = idx & 511;
    const float2* Cr = (const float2*)(g_C + (size_t)b * N9) + h2;
    float2 s0 = Cr[0],        s1 = Cr[512],      s2 = Cr[1024];
    float2 s4 = Cr[1536],     s5 = Cr[2048],     s6 = Cr[2560];
    float2 s7 = Cr[3072],     x3 = Cr[3584],     m3 = Cr[4096];
    float2 cp = ((const float2*)c_prev)[idx];

    float2 nm, nc;
    nm.x = gate_net(s0.x, s1.x, s2.x, s4.x, s5.x, s6.x, s7.x, x3.x, m3.x, cp.x, nc.x);
    nm.y = gate_net(s0.y, s1.y, s2.y, s4.y, s5.y, s6.y, s7.y, x3.y, m3.y, cp.y, nc.y);

    float2* o = (float2*)out;
    o[idx] = nm;                         // new_m
    o[BQ * 512 + idx] = nc;              // new_c
}

// ---------------- launch ----------------
extern "C" void kernel_launch(void* const* d_in, const int* in_sizes, int n_in,
                              void* d_out, int out_size) {
    const float* x      = (const float*)d_in[0];
    const float* m_prev = (const float*)d_in[1];
    const float* c_prev = (const float*)d_in[2];
    const float* w_m    = (const float*)d_in[3];
    const float* w_in   = (const float*)d_in[4];
    float* out = (float*)d_out;

    cudaFuncSetAttribute(gemm_kernel, cudaFuncAttributeMaxDynamicSharedMemorySize, SMEM_DYN);

    {   // merged pack (A blocks + B blocks overlap in one launch)
        pack_AB<<<PACK_BLOCKS, 256>>>(x, m_prev, w_in, w_m);
    }
    {   // persistent cross-tile-pipelined GEMM (steal-ahead work stealing)
        gemm_kernel<<<GRID_P, 128, SMEM_DYN>>>();
    }
    {   // gate network
        int n = BQ * 512;
        combine_kernel<<<(n + 255) / 256, 256>>>(c_prev, out);
    }
    (void)in_sizes; (void)n_in; (void)out_size;
}

// round 17
// speedup vs baseline: 1.0973x; 1.0973x over previous
#include <cuda_runtime.h>
#include <cuda_fp16.h>
#include <cstdint>

#define DINLINE __device__ __forceinline__

// ---------------- problem constants ----------------
constexpr int BQ  = 8192;   // batch rows
constexpr int HID = 1024;   // hidden
constexpr int N9  = 9216;   // packed N: 7 sum gates + x3 + m3
constexpr int KC  = 4096;   // correction K (fp16-acc phase): [xl | xh | ml | mh]
constexpr int KM  = 2048;   // main K (f32-acc phase): [xh | mh]

// GEMM tiling: 128x128 CTA tile, 4 warps, 3 stages, 2 CTA/SM, persistent
constexpr int BM = 128, BN = 128, NSTAGE = 3;
constexpr int A_STAGE_BYTES = BM * 128;                      // 16384 (128B/row)
constexpr int STAGE_BYTES   = 2 * A_STAGE_BYTES;             // 32768
constexpr int SMEM_DYN      = NSTAGE * STAGE_BYTES + 1024;

constexpr int MT = BQ / BM;   // 64
constexpr int NT = N9 / BN;   // 72
constexpr int GM = 16;        // m-supertile height (halves B DRAM re-reads)
constexpr int NTILES = MT * NT;          // 4608
constexpr int GRID_P = 296;              // 148 SMs x 2 CTAs (all resident)

// ---------------- device scratch (static globals: allowed) ----------------
__device__ __half g_Ac[(size_t)BQ * KC];   // 64 MB  corrections
__device__ __half g_Am[(size_t)BQ * KM];   // 32 MB  main
__device__ __half g_Bc[(size_t)N9 * KC];   // 72 MB
__device__ __half g_Bm[(size_t)N9 * KM];   // 36 MB
__device__ float  g_C [(size_t)BQ * N9];   // 288 MB
__device__ unsigned int g_tile_ctr;        // work-stealing cursor

// ---------------- PTX helpers (sm_80-class only) ----------------
DINLINE uint32_t smem_u32(const void* p) {
    uint32_t a;
    asm("{ .reg .u64 t; cvta.to.shared.u64 t, %1; cvt.u32.u64 %0, t; }"
        : "=r"(a) : "l"(p));
    return a;
}

DINLINE void cp16(uint32_t dst, const void* src) {
    asm volatile("cp.async.cg.shared.global [%0], [%1], 16;" :: "r"(dst), "l"(src));
}
DINLINE void cp_commit() { asm volatile("cp.async.commit_group;" ::: "memory"); }
DINLINE void cp_wait1()  { asm volatile("cp.async.wait_group 1;" ::: "memory"); }

DINLINE void ldsm4(uint32_t& r0, uint32_t& r1, uint32_t& r2, uint32_t& r3,
                   uint32_t addr) {
    asm volatile("ldmatrix.sync.aligned.m8n8.x4.shared.b16 {%0,%1,%2,%3}, [%4];"
                 : "=r"(r0), "=r"(r1), "=r"(r2), "=r"(r3) : "r"(addr));
}

// fp16 x fp16 -> f32 accumulate, acc stored as uint32 bits
DINLINE void mma_f32(uint32_t* c, const uint32_t* a, const uint32_t* b) {
    asm volatile(
        "{\n\t.reg .f32 p0,p1,p2,p3;\n\t"
        "mov.b32 p0,%0; mov.b32 p1,%1; mov.b32 p2,%2; mov.b32 p3,%3;\n\t"
        "mma.sync.aligned.m16n8k16.row.col.f32.f16.f16.f32 "
        "{p0,p1,p2,p3}, {%4,%5,%6,%7}, {%8,%9}, {p0,p1,p2,p3};\n\t"
        "mov.b32 %0,p0; mov.b32 %1,p1; mov.b32 %2,p2; mov.b32 %3,p3;\n\t}"
        : "+r"(c[0]), "+r"(c[1]), "+r"(c[2]), "+r"(c[3])
        : "r"(a[0]), "r"(a[1]), "r"(a[2]), "r"(a[3]), "r"(b[0]), "r"(b[1]));
}

// fp16 x fp16 -> f16 accumulate (2 packed regs)
DINLINE void mma_f16(uint32_t* c, const uint32_t* a, const uint32_t* b) {
    asm volatile(
        "mma.sync.aligned.m16n8k16.row.col.f16.f16.f16.f16 "
        "{%0,%1}, {%2,%3,%4,%5}, {%6,%7}, {%0,%1};"
        : "+r"(c[0]), "+r"(c[1])
        : "r"(a[0]), "r"(a[1]), "r"(a[2]), "r"(a[3]), "r"(b[0]), "r"(b[1]));
}

DINLINE __half2 u32_as_half2(uint32_t u) {
    __half2 h;
    *(uint32_t*)&h = u;
    return h;
}

// fast transcendentals: MUFU ex2 + MUFU rcp (__fdividef), saturate at +-inf
DINLINE float fsig(float v)  { return __fdividef(1.0f, 1.0f + __expf(-v)); }
DINLINE float ftanh(float v) { return 1.0f - __fdividef(2.0f, __expf(2.0f * v) + 1.0f); }

// ---------------- pack kernels ----------------
// Am row b: [xh | mh]. Ac row b: [xl | xh | ml | mh]  (all fp16)
__global__ void pack_A(const float* __restrict__ x, const float* __restrict__ m) {
    size_t idx = (size_t)blockIdx.x * blockDim.x + threadIdx.x;
    if (idx == 0) g_tile_ctr = GRID_P;      // reset work-stealing cursor
    if (idx >= (size_t)BQ * 256) return;
    size_t b = idx >> 8;
    int k4 = (int)(idx & 255) * 4;

    float xs[4], ms[4];
    *(float4*)xs = *(const float4*)(x + b * 1024 + k4);
    *(float4*)ms = *(const float4*)(m + b * 1024 + k4);

    unsigned short xh[4], xl[4], mh[4], ml[4];
#pragma unroll
    for (int c = 0; c < 4; c++) {
        __half h = __float2half_rn(xs[c]);
        xh[c] = __half_as_ushort(h);
        xl[c] = __half_as_ushort(__float2half_rn(xs[c] - __half2float(h)));
        h = __float2half_rn(ms[c]);
        mh[c] = __half_as_ushort(h);
        ml[c] = __half_as_ushort(__float2half_rn(ms[c] - __half2float(h)));
    }
    *(uint2*)&g_Am[b * KM + k4]        = *(uint2*)xh;
    *(uint2*)&g_Am[b * KM + 1024 + k4] = *(uint2*)mh;
    *(uint2*)&g_Ac[b * KC + k4]        = *(uint2*)xl;
    *(uint2*)&g_Ac[b * KC + 1024 + k4] = *(uint2*)xh;
    *(uint2*)&g_Ac[b * KC + 2048 + k4] = *(uint2*)ml;
    *(uint2*)&g_Ac[b * KC + 3072 + k4] = *(uint2*)mh;
}

// Bm row n: [wih | wmh]. Bc row n: [wih | wil | wmh | wml]
// (corr pairing: xl*wih + xh*wil + ml*wmh + mh*wml)
__global__ void pack_B(const float* __restrict__ wi, const float* __restrict__ wm) {
    __shared__ float t[32][33];
    int ct = blockIdx.x;             // col tile over 8192
    int kt = blockIdx.y;             // k tile over 1024
    int z  = blockIdx.z;             // 0 = w_inputs, 1 = w_m
    const float* w = z ? wm : wi;
    int col0 = ct * 32, k0 = kt * 32;
    int tx = threadIdx.x, ty = threadIdx.y;     // 16 x 16
    for (int r = ty; r < 32; r += 16) {
        t[r][tx]      = w[(size_t)(k0 + r) * 8192 + col0 + tx];
        t[r][tx + 16] = w[(size_t)(k0 + r) * 8192 + col0 + tx + 16];
    }
    __syncthreads();
    for (int r = ty; r < 32; r += 16) {
        int col = col0 + r;
        float v0 = t[2 * tx][r];         // = w[k0+2tx][col]
        float v1 = t[2 * tx + 1][r];     // = w[k0+2tx+1][col]
        __half h0 = __float2half_rn(v0), h1 = __float2half_rn(v1);
        __half l0 = __float2half_rn(v0 - __half2float(h0));
        __half l1 = __float2half_rn(v1 - __half2float(h1));
        __half2 hi2 = __halves2half2(h0, h1);
        __half2 lo2 = __halves2half2(l0, l1);
        int g = col >> 10, h = col & 1023;
        size_t n;
        if (g == 3) n = z ? (size_t)(8192 + h) : (size_t)(7168 + h);
        else        n = (size_t)((g < 3 ? g : g - 1) * 1024 + h);
        int kk = k0 + 2 * tx;
        *(__half2*)&g_Bm[n * KM + z * 1024 + kk]        = hi2;
        *(__half2*)&g_Bc[n * KC + z * 2048 + kk]        = hi2;
        *(__half2*)&g_Bc[n * KC + z * 2048 + 1024 + kk] = lo2;
    }
}

// ---------------- GEMM: persistent, fp16-acc corr phase + f32-acc main ----
__global__ __launch_bounds__(128, 2)
void gemm_kernel() {
    extern __shared__ char dsmem[];
    __shared__ unsigned int s_next;
    char* tilep = (char*)(((uintptr_t)dsmem + 1023) & ~(uintptr_t)1023);
    uint32_t tile_base = smem_u32(tilep);

    int tid = threadIdx.x;
    int wid = tid >> 5;
    int lid = tid & 31;
    int wmo = (wid & 1) * 64;    // warp m-offset (2 warps in m)
    int wno = (wid >> 1) * 64;   // warp n-offset (2 warps in n)

    int rowA = wmo + (lid & 15);                      // + mf*16
    int kAby = (lid >> 4) * 16;                       // + ks*32 bytes
    int rowB = wno + (lid & 7) + (lid >> 4) * 8;      // + nf2*16
    int kBby = ((lid >> 3) & 1) * 16;                 // + ks*32 bytes

    unsigned int tile = blockIdx.x;

    while (tile < NTILES) {
        // supertile mapping (bands of GM m-tiles sweep all n)
        int mt = (tile / (GM * NT)) * GM + (tile % GM);
        int nt = (tile / GM) % NT;
        int m0 = mt * BM;
        int n0 = nt * BN;

        // region: byte offsets within packed rows + stage counts (128B each)
        int cbeg, nc, mbeg, nm;
        if (n0 >= 8192)      { cbeg = 4096; nc = 32; mbeg = 2048; nm = 16; } // m3
        else if (n0 >= 7168) { cbeg = 0;    nc = 32; mbeg = 0;    nm = 16; } // x3
        else                 { cbeg = 0;    nc = 64; mbeg = 0;    nm = 32; } // sums
        int NS = nc + nm;

        const char* pAc = (const char*)g_Ac + (size_t)m0 * (KC * 2) + cbeg;
        const char* pAm = (const char*)g_Am + (size_t)m0 * (KM * 2) + mbeg;
        const char* pBc = (const char*)g_Bc + (size_t)n0 * (KC * 2) + cbeg;
        const char* pBm = (const char*)g_Bm + (size_t)n0 * (KM * 2) + mbeg;

        auto fill_stage = [&](int s, int i) {
            bool corr = (i < nc);
            const char* gA = corr ? pAc + i * 128 : pAm + (i - nc) * 128;
            const char* gB = corr ? pBc + i * 128 : pBm + (i - nc) * 128;
            size_t stride = corr ? (size_t)(KC * 2) : (size_t)(KM * 2);
            uint32_t baseA = tile_base + s * STAGE_BYTES;
            uint32_t baseB = baseA + A_STAGE_BYTES;
#pragma unroll
            for (int j = 0; j < 16; j++) {
                int ch = tid + (j << 7);           // 0..2047
                int rr = (ch >> 3) & 127;
                int cc = ch & 7;
                uint32_t off = (uint32_t)((rr << 7) + (cc << 4));
                uint32_t sw  = off ^ ((off >> 3) & 0x70);
                const char* src = ((ch < 1024) ? gA : gB) + (size_t)rr * stride + (cc << 4);
                cp16(((ch < 1024) ? baseA : baseB) + sw, src);
            }
        };

        // accumulator union: f16 pair in [0..1] during corr phase,
        // f32 bits in [0..3] after the in-place expansion
        uint32_t acc[4][8][4];
#pragma unroll
        for (int mf = 0; mf < 4; mf++)
#pragma unroll
            for (int nf = 0; nf < 8; nf++) {
                acc[mf][nf][0] = 0u; acc[mf][nf][1] = 0u;
                acc[mf][nf][2] = 0u; acc[mf][nf][3] = 0u;
            }

        fill_stage(0, 0); cp_commit();
        fill_stage(1, 1); cp_commit();

        uint32_t aF[2][4][4];
        uint32_t bF[2][8][2];

        auto load_frags = [&](int buf, uint32_t sA, uint32_t sB, int ks) {
#pragma unroll
            for (int mf = 0; mf < 4; mf++) {
                uint32_t off = (uint32_t)((rowA + mf * 16) << 7);
                uint32_t addr = sA + off + (((uint32_t)(kAby + ks * 32)) ^ ((off >> 3) & 0x70));
                ldsm4(aF[buf][mf][0], aF[buf][mf][1], aF[buf][mf][2], aF[buf][mf][3], addr);
            }
#pragma unroll
            for (int nf2 = 0; nf2 < 4; nf2++) {
                uint32_t off = (uint32_t)((rowB + nf2 * 16) << 7);
                uint32_t addr = sB + off + (((uint32_t)(kBby + ks * 32)) ^ ((off >> 3) & 0x70));
                uint32_t r0, r1, r2, r3;
                ldsm4(r0, r1, r2, r3, addr);
                bF[buf][nf2 * 2][0] = r0;      bF[buf][nf2 * 2][1] = r1;
                bF[buf][nf2 * 2 + 1][0] = r2;  bF[buf][nf2 * 2 + 1][1] = r3;
            }
        };

        for (int i = 0; i < NS; i++) {
            int s = i - (i / NSTAGE) * NSTAGE;            // i % 3
            // SAFE order: wait fill(i); barrier (readers of stage (i+2)%3
            // done); first frag loads; only then refill that stage.
            cp_wait1();
            __syncthreads();

            if (i == nc) {   // phase boundary: expand fp16 acc -> f32 bits
#pragma unroll
                for (int mf = 0; mf < 4; mf++)
#pragma unroll
                    for (int nf = 0; nf < 8; nf++) {
                        float2 lo = __half22float2(u32_as_half2(acc[mf][nf][0]));
                        float2 hi = __half22float2(u32_as_half2(acc[mf][nf][1]));
                        acc[mf][nf][0] = __float_as_uint(lo.x);
                        acc[mf][nf][1] = __float_as_uint(lo.y);
                        acc[mf][nf][2] = __float_as_uint(hi.x);
                        acc[mf][nf][3] = __float_as_uint(hi.y);
                    }
            }

            uint32_t sA = tile_base + s * STAGE_BYTES;
            uint32_t sB = sA + A_STAGE_BYTES;
            load_frags(0, sA, sB, 0);                     // start compute feed
            if (i + 2 < NS) fill_stage((s + 2 >= NSTAGE) ? s + 2 - NSTAGE : s + 2, i + 2);
            cp_commit();

            if (i < nc) {
#pragma unroll
                for (int ks = 0; ks < 4; ks++) {
                    int cur = ks & 1;
                    if (ks < 3) load_frags(cur ^ 1, sA, sB, ks + 1);
#pragma unroll
                    for (int mf = 0; mf < 4; mf++)
#pragma unroll
                        for (int nf = 0; nf < 8; nf++)
                            mma_f16(acc[mf][nf], aF[cur][mf], bF[cur][nf]);
                }
            } else {
#pragma unroll
                for (int ks = 0; ks < 4; ks++) {
                    int cur = ks & 1;
                    if (ks < 3) load_frags(cur ^ 1, sA, sB, ks + 1);
#pragma unroll
                    for (int mf = 0; mf < 4; mf++)
#pragma unroll
                        for (int nf = 0; nf < 8; nf++)
                            mma_f32(acc[mf][nf], aF[cur][mf], bF[cur][nf]);
                }
            }
        }

        // epilogue: float2 stores
        int rr = lid >> 2;
        int cc2 = (lid & 3) * 2;
#pragma unroll
        for (int mf = 0; mf < 4; mf++) {
#pragma unroll
            for (int nf = 0; nf < 8; nf++) {
                int m = m0 + wmo + mf * 16 + rr;
                int n = n0 + wno + nf * 8 + cc2;
                float2 v0 = make_float2(__uint_as_float(acc[mf][nf][0]),
                                        __uint_as_float(acc[mf][nf][1]));
                float2 v1 = make_float2(__uint_as_float(acc[mf][nf][2]),
                                        __uint_as_float(acc[mf][nf][3]));
                *(float2*)&g_C[(size_t)m * N9 + n] = v0;
                *(float2*)&g_C[(size_t)(m + 8) * N9 + n] = v1;
            }
        }

        // steal next tile
        if (tid == 0) s_next = atomicAdd(&g_tile_ctr, 1u);
        __syncthreads();                 // also guards smem reuse next tile
        tile = s_next;
    }
}

// ---------------- combine: gate network (float2, fast transcendentals) ----
DINLINE float gate_net(float s0, float s1, float s2, float s4, float s5,
                       float s6, float s7, float x3, float m3,
                       float cp, float& nc) {
    float l10 = fsig(s0);
    float l11 = fmaxf(s1, 0.0f);
    float l12 = fsig(s2);
    float l13 = fmaxf(x3 * m3, 0.0f);
    float l14 = ftanh(s4);
    float l15 = fsig(s5);
    float l16 = ftanh(s6);
    float l17 = fsig(s7);
    float l20 = ftanh(l10 * l11);
    float l21 = ftanh(l12 + l13);
    float l22 = ftanh(l14 * l15);
    float l23 = fsig(l16 + l17);
    l20 = ftanh(l20 + cp);
    nc = l20 * l21;
    float l31 = ftanh(l22 + l23);
    return ftanh(nc * l31);
}

__global__ void combine_kernel(const float* __restrict__ c_prev, float* __restrict__ out) {
    int idx = blockIdx.x * blockDim.x + threadIdx.x;      // < BQ*512
    if (idx >= BQ * 512) return;
    int b  = idx >> 9;
    int h2 = idx & 511;
    const float2* Cr = (const float2*)(g_C + (size_t)b * N9) + h2;
    float2 s0 = Cr[0],        s1 = Cr[512],      s2 = Cr[1024];
    float2 s4 = Cr[1536],     s5 = Cr[2048],     s6 = Cr[2560];
    float2 s7 = Cr[3072],     x3 = Cr[3584],     m3 = Cr[4096];
    float2 cp = ((const float2*)c_prev)[idx];

    float2 nm, nc;
    nm.x = gate_net(s0.x, s1.x, s2.x, s4.x, s5.x, s6.x, s7.x, x3.x, m3.x, cp.x, nc.x);
    nm.y = gate_net(s0.y, s1.y, s2.y, s4.y, s5.y, s6.y, s7.y, x3.y, m3.y, cp.y, nc.y);

    float2* o = (float2*)out;
    o[idx] = nm;                         // new_m
    o[BQ * 512 + idx] = nc;              // new_c
}

// ---------------- launch ----------------
extern "C" void kernel_launch(void* const* d_in, const int* in_sizes, int n_in,
                              void* d_out, int out_size) {
    const float* x      = (const float*)d_in[0];
    const float* m_prev = (const float*)d_in[1];
    const float* c_prev = (const float*)d_in[2];
    const float* w_m    = (const float*)d_in[3];
    const float* w_in   = (const float*)d_in[4];
    float* out = (float*)d_out;

    cudaFuncSetAttribute(gemm_kernel, cudaFuncAttributeMaxDynamicSharedMemorySize, SMEM_DYN);

    {   // pack A (fp16 hi + fp16 residual) + cursor reset
        size_t n = (size_t)BQ * 256;
        pack_A<<<(unsigned)((n + 255) / 256), 256>>>(x, m_prev);
    }
    {   // pack B (transpose + fp16 hi/lo, half2 stores)
        dim3 grid(256, 32, 2), blk(16, 16);
        pack_B<<<grid, blk>>>(w_in, w_m);
    }
    {   // persistent two-phase GEMM (work-stealing)
        gemm_kernel<<<GRID_P, 128, SMEM_DYN>>>();
    }
    {   // gate network
        int n = BQ * 512;
        combine_kernel<<<(n + 255) / 256, 256>>>(c_prev, out);
    }
    (void)in_sizes; (void)n_in; (void)out_size;
}